// round 9
// baseline (speedup 1.0000x reference)
#include <cuda_runtime.h>
#include <cuda_fp16.h>
#include <stdint.h>

#define S_    2048
#define B_    2
#define D_    1024
#define H_    16
#define BH_   32
#define ROWS_ 4096
#define QLD_  3072
#define ARS_  6144   // B_*QLD_ : stride between seq rows in g_qkv

// ---- scratch (static device globals; no allocation) ----
__device__ float  g_qkv[(size_t)ROWS_ * 3072];         // q cols f32 (k,v blocks unused)
__device__ __half g_kh [(size_t)ROWS_ * 1024];         // K fp16 [s*B+b][h*64+d]
__device__ __half g_vh [(size_t)ROWS_ * 1024];         // V fp16 [s*B+b][h*64+d]
__device__ float  g_r  [(size_t)S_ * D_];              // [t][h*64+d]
__device__ __half g_bd [(size_t)BH_ * S_ * S_];        // Draw per (b,h), fp16
__device__ float  g_att[(size_t)ROWS_ * D_];           // attn_vec
__device__ float  g_y  [(size_t)ROWS_ * D_];           // x + attn_out

// ---------------- mma / cp.async / ldmatrix helpers ----------------
__device__ __forceinline__ void mma8(float* d, const uint32_t* a,
                                     const uint32_t* b, const float* c) {
    asm volatile(
        "mma.sync.aligned.m16n8k8.row.col.f32.tf32.tf32.f32 "
        "{%0,%1,%2,%3}, {%4,%5,%6,%7}, {%8,%9}, {%10,%11,%12,%13};\n"
        : "=f"(d[0]), "=f"(d[1]), "=f"(d[2]), "=f"(d[3])
        : "r"(a[0]), "r"(a[1]), "r"(a[2]), "r"(a[3]), "r"(b[0]), "r"(b[1]),
          "f"(c[0]), "f"(c[1]), "f"(c[2]), "f"(c[3]));
}
__device__ __forceinline__ void mma16h(float* d, const uint32_t* a,
                                       const uint32_t* b, const float* c) {
    asm volatile(
        "mma.sync.aligned.m16n8k16.row.col.f32.f16.f16.f32 "
        "{%0,%1,%2,%3}, {%4,%5,%6,%7}, {%8,%9}, {%10,%11,%12,%13};\n"
        : "=f"(d[0]), "=f"(d[1]), "=f"(d[2]), "=f"(d[3])
        : "r"(a[0]), "r"(a[1]), "r"(a[2]), "r"(a[3]), "r"(b[0]), "r"(b[1]),
          "f"(c[0]), "f"(c[1]), "f"(c[2]), "f"(c[3]));
}
__device__ __forceinline__ uint32_t f2u(float x) { return __float_as_uint(x); }
__device__ __forceinline__ uint32_t h2(float lo, float hi) {
    uint32_t d;
    asm("cvt.rn.f16x2.f32 %0, %1, %2;\n" : "=r"(d) : "f"(hi), "f"(lo));
    return d;   // d.lo = lo, d.hi = hi
}
__device__ __forceinline__ void stg_cs32(void* p, uint32_t v) {
    asm volatile("st.global.cs.b32 [%0], %1;\n" :: "l"(p), "r"(v));
}
__device__ __forceinline__ float ldg_cs_h(const __half* p) {
    uint16_t u;
    asm volatile("ld.global.cs.b16 %0, [%1];\n" : "=h"(u) : "l"(p));
    __half hv = __ushort_as_half(u);
    return __half2float(hv);
}
__device__ __forceinline__ void cpa16(uint32_t s, const void* g) {
    asm volatile("cp.async.cg.shared.global [%0], [%1], 16;\n" :: "r"(s), "l"(g));
}
__device__ __forceinline__ void cpcommit() { asm volatile("cp.async.commit_group;\n"); }
template <int N> __device__ __forceinline__ void cpwait() {
    asm volatile("cp.async.wait_group %0;\n" :: "n"(N));
}
__device__ __forceinline__ void ldsm4(uint32_t* r, uint32_t a) {
    asm volatile("ldmatrix.sync.aligned.m8n8.x4.shared.b16 {%0,%1,%2,%3}, [%4];\n"
        : "=r"(r[0]), "=r"(r[1]), "=r"(r[2]), "=r"(r[3]) : "r"(a));
}
__device__ __forceinline__ void ldsm4t(uint32_t* r, uint32_t a) {
    asm volatile("ldmatrix.sync.aligned.m8n8.x4.trans.shared.b16 {%0,%1,%2,%3}, [%4];\n"
        : "=r"(r[0]), "=r"(r[1]), "=r"(r[2]), "=r"(r[3]) : "r"(a));
}
__device__ __forceinline__ float ex2(float x) {
    float y; asm("ex2.approx.f32 %0, %1;" : "=f"(y) : "f"(x)); return y;
}

// ============================================================
// Projection GEMM, K=1024 fixed, tile 128x128x32, cp.async 2-stage.
// MODE 0: q cols -> g_qkv f32, K cols -> g_kh fp16, V cols -> g_vh fp16
// MODE 1: g_r = A@B    MODE 2: g_y = g_att@B + Xres
// ============================================================
template <int MODE>
__global__ __launch_bounds__(256, 2) void pgemm(const float* __restrict__ A,
                                                const float* __restrict__ Bw,
                                                const float* __restrict__ Xres,
                                                int N)
{
    extern __shared__ float sm[];
    float* As = sm;               // 2 x 128 x 36
    float* Bs = sm + 9216;        // 2 x 32  x 136
    const float* Ap = (MODE == 2) ? (const float*)g_att : A;
    float* C = (MODE == 0) ? g_qkv : (MODE == 1) ? g_r : g_y;

    int tid = threadIdx.x, l = tid & 31, w = tid >> 5, wm = w >> 1, wn = w & 1;
    size_t m0 = (size_t)blockIdx.y * 128, n0 = (size_t)blockIdx.x * 128;
    uint32_t sA = (uint32_t)__cvta_generic_to_shared(As);
    uint32_t sB = (uint32_t)__cvta_generic_to_shared(Bs);

    float acc[2][8][4] = {};

#define STAGE(IT, BUF)                                                          \
    {                                                                           \
        int kk = (IT) * 32;                                                     \
        uint32_t ab = sA + (BUF) * 4608 * 4;                                    \
        _Pragma("unroll")                                                       \
        for (int t = 0; t < 4; t++) {                                           \
            int idx = tid + t * 256; int r = idx >> 3, c4 = (idx & 7) << 2;     \
            cpa16(ab + (r * 36 + c4) * 4, Ap + (m0 + r) * 1024 + kk + c4);      \
        }                                                                       \
        uint32_t bb = sB + (BUF) * 4352 * 4;                                    \
        _Pragma("unroll")                                                       \
        for (int t = 0; t < 4; t++) {                                           \
            int idx = tid + t * 256; int r = idx >> 5, c4 = (idx & 31) << 2;    \
            cpa16(bb + (r * 136 + c4) * 4, Bw + (size_t)(kk + r) * N + n0 + c4);\
        }                                                                       \
        cpcommit();                                                             \
    }

    STAGE(0, 0);
    for (int it = 0; it < 32; it++) {
        int buf = it & 1;
        if (it + 1 < 32) { STAGE(it + 1, buf ^ 1); cpwait<1>(); }
        else             { cpwait<0>(); }
        __syncthreads();
        const float* As_ = As + buf * 4608;
        const float* Bs_ = Bs + buf * 4352;
#pragma unroll
        for (int k8 = 0; k8 < 4; k8++) {
            uint32_t a[2][4];
#pragma unroll
            for (int mt = 0; mt < 2; mt++) {
                int r = wm * 32 + mt * 16 + (l >> 2);
                a[mt][0] = f2u(As_[r * 36 + k8 * 8 + (l & 3)]);
                a[mt][1] = f2u(As_[(r + 8) * 36 + k8 * 8 + (l & 3)]);
                a[mt][2] = f2u(As_[r * 36 + k8 * 8 + (l & 3) + 4]);
                a[mt][3] = f2u(As_[(r + 8) * 36 + k8 * 8 + (l & 3) + 4]);
            }
#pragma unroll
            for (int nt = 0; nt < 8; nt++) {
                uint32_t bf[2];
                int cb = wn * 64 + nt * 8 + (l >> 2);
                bf[0] = f2u(Bs_[(k8 * 8 + (l & 3)) * 136 + cb]);
                bf[1] = f2u(Bs_[(k8 * 8 + (l & 3) + 4) * 136 + cb]);
#pragma unroll
                for (int mt = 0; mt < 2; mt++)
                    mma8(acc[mt][nt], a[mt], bf, acc[mt][nt]);
            }
        }
        __syncthreads();
    }
#undef STAGE

    if (MODE == 0 && n0 >= 1024) {
        // K / V columns: write fp16 copies only (f32 never read)
        __half* dst = (n0 >= 2048) ? g_vh : g_kh;
        size_t cb = n0 - ((n0 >= 2048) ? 2048 : 1024);
#pragma unroll
        for (int mt = 0; mt < 2; mt++) {
            size_t r0 = m0 + wm * 32 + mt * 16 + (l >> 2);
#pragma unroll
            for (int nt = 0; nt < 8; nt++) {
                size_t c = cb + wn * 64 + nt * 8 + 2 * (l & 3);
                *(__half2*)(dst + r0 * 1024 + c) =
                    __floats2half2_rn(acc[mt][nt][0], acc[mt][nt][1]);
                *(__half2*)(dst + (r0 + 8) * 1024 + c) =
                    __floats2half2_rn(acc[mt][nt][2], acc[mt][nt][3]);
            }
        }
        return;
    }
#pragma unroll
    for (int mt = 0; mt < 2; mt++) {
        size_t r0 = m0 + wm * 32 + mt * 16 + (l >> 2);
#pragma unroll
        for (int nt = 0; nt < 8; nt++) {
            size_t c = n0 + wn * 64 + nt * 8 + 2 * (l & 3);
            float2 v0 = make_float2(acc[mt][nt][0], acc[mt][nt][1]);
            float2 v1 = make_float2(acc[mt][nt][2], acc[mt][nt][3]);
            if (MODE == 2) {
                float2 x0 = *(const float2*)(Xres + r0 * N + c);
                float2 x1 = *(const float2*)(Xres + (r0 + 8) * N + c);
                v0.x += x0.x; v0.y += x0.y; v1.x += x1.x; v1.y += x1.y;
            }
            *(float2*)(C + r0 * N + c) = v0;
            *(float2*)(C + (r0 + 8) * N + c) = v1;
        }
    }
}

// ============================================================
// Draw = (q + pos_bias_v) @ r^T per (b,h). 128x128, K=64, ldmatrix.
// Output fp16 with streaming stores (written once, read once).
// ============================================================
__global__ __launch_bounds__(256, 2) void bd_gemm(const float* __restrict__ pbv)
{
    extern __shared__ float sm[];
    float* Qs = sm;               // 128 x 68
    float* Rs = sm + 8704;        // 128 x 68
    int tid = threadIdx.x, l = tid & 31, w = tid >> 5;
    int bh = blockIdx.z, b = bh >> 4, h = bh & 15;
    int i0 = blockIdx.y * 128, t0 = blockIdx.x * 128;
    const float* Qg = g_qkv + (size_t)b * QLD_ + h * 64;
    const float* Rg = g_r + h * 64;
    const float* bias = pbv + h * 64;

#pragma unroll
    for (int t = 0; t < 8; t++) {
        int idx = tid + t * 256; int r = idx >> 4, c4 = (idx & 15) << 2;
        float4 a4 = *(const float4*)(Qg + (size_t)(i0 + r) * ARS_ + c4);
        float4 u4 = *(const float4*)(bias + c4);
        a4.x += u4.x; a4.y += u4.y; a4.z += u4.z; a4.w += u4.w;
        *(float4*)&Qs[r * 68 + c4] = a4;
        *(float4*)&Rs[r * 68 + c4] = *(const float4*)(Rg + (size_t)(t0 + r) * D_ + c4);
    }
    __syncthreads();

    uint32_t sQ = (uint32_t)__cvta_generic_to_shared(Qs);
    uint32_t sR = (uint32_t)__cvta_generic_to_shared(Rs);
    uint32_t aoff = ((w * 16 + ((l >> 3) & 1) * 8 + (l & 7)) * 68 + ((l >> 4) & 1) * 4) * 4;
    uint32_t boff = ((((l >> 4) & 1) * 8 + (l & 7)) * 68 + ((l >> 3) & 1) * 4) * 4;

    uint32_t qa[8][4];
#pragma unroll
    for (int k8 = 0; k8 < 8; k8++) ldsm4(qa[k8], sQ + aoff + k8 * 32);

    float acc[16][4] = {};
#pragma unroll
    for (int k8 = 0; k8 < 8; k8++)
#pragma unroll
        for (int np = 0; np < 8; np++) {
            uint32_t kb[4];
            ldsm4(kb, sR + boff + np * 16 * 272 + k8 * 32);
            mma8(acc[2 * np],     qa[k8], kb,     acc[2 * np]);
            mma8(acc[2 * np + 1], qa[k8], kb + 2, acc[2 * np + 1]);
        }

    __half* out = g_bd + (size_t)bh * S_ * S_;
    int gr = i0 + w * 16 + (l >> 2);
#pragma unroll
    for (int nt = 0; nt < 16; nt++) {
        int gc = t0 + nt * 8 + 2 * (l & 3);
        stg_cs32(out + (size_t)gr * S_ + gc,       h2(acc[nt][0], acc[nt][1]));
        stg_cs32(out + (size_t)(gr + 8) * S_ + gc, h2(acc[nt][2], acc[nt][3]));
    }
}

// ============================================================
// Fused attention, all-fp16 mma paths:
//  AC: (q+u) fp16 x K fp16, m16n8k16 (Q smem fp16, K via ldsm4)
//  PV: P fp16 (reg cvt, no shuffles) x V fp16 (ldsm4t)
// BD (fp16) gather pipelined in registers. smem 55 KB, 2 CTAs/SM.
// ============================================================
__device__ __forceinline__ float bdval(const __half* bd, int i, int j)
{
    if (j <= i)      return ldg_cs_h(bd + (size_t)i * S_ + (S_ - 1 + j - i));
    if (j == i + 1)  return 0.f;
    return ldg_cs_h(bd + (size_t)(i + 1) * S_ + (j - i - 2));
}

__global__ __launch_bounds__(256, 2) void fattn(const float* __restrict__ pbu)
{
    extern __shared__ __half smh[];
    __half* Qsh = smh;                      // 128 x 72 fp16 (persistent)
    __half* Ksh = smh + 9216;               // 128 x 72 fp16
    __half* Vsh = smh + 18432;              // 128 x 72 fp16
    int tid = threadIdx.x, l = tid & 31, w = tid >> 5;
    int bh = blockIdx.y, b = bh >> 4, h = bh & 15;
    int i0 = blockIdx.x * 128;
    const float*  Qg = g_qkv + (size_t)b * QLD_ + h * 64;
    const __half* Kg = g_kh + (size_t)b * 1024 + h * 64;   // row stride 2048
    const __half* Vg = g_vh + (size_t)b * 1024 + h * 64;   // row stride 2048
    const __half* bd = g_bd + (size_t)bh * S_ * S_;
    const float* bias = pbu + h * 64;
    uint32_t sQ = (uint32_t)__cvta_generic_to_shared(Qsh);
    uint32_t sK = (uint32_t)__cvta_generic_to_shared(Ksh);
    uint32_t sV = (uint32_t)__cvta_generic_to_shared(Vsh);

    // (q + bias_u) -> fp16 smem; prefetch K0 (group), V0 (group)
#pragma unroll
    for (int t = 0; t < 8; t++) {
        int idx = tid + t * 256; int r = idx >> 4, c4 = (idx & 15) << 2;
        float4 a4 = *(const float4*)(Qg + (size_t)(i0 + r) * ARS_ + c4);
        float4 u4 = *(const float4*)(bias + c4);
        *(__half2*)(Qsh + r * 72 + c4)     = __floats2half2_rn(a4.x + u4.x, a4.y + u4.y);
        *(__half2*)(Qsh + r * 72 + c4 + 2) = __floats2half2_rn(a4.z + u4.z, a4.w + u4.w);
    }
#pragma unroll
    for (int t = 0; t < 4; t++) {
        int idx = tid + t * 256; int r = idx >> 3, c8 = (idx & 7) << 3;
        cpa16(sK + (r * 72 + c8) * 2, Kg + (size_t)r * 2048 + c8);
    }
    cpcommit();
#pragma unroll
    for (int t = 0; t < 4; t++) {
        int idx = tid + t * 256; int r = idx >> 3, c8 = (idx & 7) << 3;
        cpa16(sV + (r * 72 + c8) * 2, Vg + (size_t)r * 2048 + c8);
    }
    cpcommit();

    // fp16 A-frag (Q rows w*16..w*16+15):
    uint32_t qoff  = (uint32_t)((w * 16 + (l & 7) + ((l >> 3) & 1) * 8) * 144
                                + ((l >> 4) & 1) * 16);
    // fp16 B-frag from row-major K (n = row, k-pairs contiguous):
    uint32_t kboff = (uint32_t)(((l & 7) + (l >> 4) * 8) * 144 + ((l >> 3) & 1) * 16);
    uint32_t vrbase = (uint32_t)((l & 7) + ((l >> 3) & 1) * 8);
    uint32_t vcoff  = (uint32_t)((l >> 4) * 8);

    float o[8][4] = {};
    float bdbuf[32];
    float mrow0 = -1e30f, mrow1 = -1e30f, lsum0 = 0.f, lsum1 = 0.f;
    int tc = l & 3;
    int lr0 = w * 16 + (l >> 2);
    int row0 = i0 + lr0, row1 = row0 + 8;
    const float CS = 0.1803368801111204f;   // 0.125 * log2(e)

#define LDBD(JB)                                                                \
    _Pragma("unroll")                                                           \
    for (int nt = 0; nt < 8; nt++) {                                            \
        int c0 = (JB) + nt * 8 + 2 * tc;                                        \
        bdbuf[nt * 4 + 0] = bdval(bd, row0, c0);                                \
        bdbuf[nt * 4 + 1] = bdval(bd, row0, c0 + 1);                            \
        bdbuf[nt * 4 + 2] = bdval(bd, row1, c0);                                \
        bdbuf[nt * 4 + 3] = bdval(bd, row1, c0 + 1);                            \
    }

    LDBD(0)              // BD for iter0/half0 — overlaps K0/V0 arrival
    __syncthreads();     // Qsh visible to ldmatrix

#define AC_MMA(HALF)                                                            \
    _Pragma("unroll")                                                           \
    for (int nt = 0; nt < 8; nt++)                                              \
        p[nt][0] = p[nt][1] = p[nt][2] = p[nt][3] = 0.f;                        \
    _Pragma("unroll")                                                           \
    for (int ks = 0; ks < 4; ks++) {                                            \
        uint32_t qf[4];                                                         \
        ldsm4(qf, sQ + qoff + ks * 32);                                         \
        _Pragma("unroll")                                                       \
        for (int np = 0; np < 4; np++) {                                        \
            uint32_t kb[4];                                                     \
            ldsm4(kb, sK + kboff + ((HALF) * 64 + np * 16) * 144 + ks * 32);    \
            mma16h(p[2 * np],     qf, kb,     p[2 * np]);                       \
            mma16h(p[2 * np + 1], qf, kb + 2, p[2 * np + 1]);                   \
        }                                                                       \
    }

#define SOFTMAX_STEP()                                                          \
    {                                                                           \
        float mx0 = -1e30f, mx1 = -1e30f;                                       \
        _Pragma("unroll")                                                       \
        for (int nt = 0; nt < 8; nt++) {                                        \
            float s;                                                            \
            s = (p[nt][0] + bdbuf[nt*4+0]) * CS; p[nt][0] = s; mx0 = fmaxf(mx0, s); \
            s = (p[nt][1] + bdbuf[nt*4+1]) * CS; p[nt][1] = s; mx0 = fmaxf(mx0, s); \
            s = (p[nt][2] + bdbuf[nt*4+2]) * CS; p[nt][2] = s; mx1 = fmaxf(mx1, s); \
            s = (p[nt][3] + bdbuf[nt*4+3]) * CS; p[nt][3] = s; mx1 = fmaxf(mx1, s); \
        }                                                                       \
        mx0 = fmaxf(mx0, __shfl_xor_sync(~0u, mx0, 1));                         \
        mx0 = fmaxf(mx0, __shfl_xor_sync(~0u, mx0, 2));                         \
        mx1 = fmaxf(mx1, __shfl_xor_sync(~0u, mx1, 1));                         \
        mx1 = fmaxf(mx1, __shfl_xor_sync(~0u, mx1, 2));                         \
        float mn0 = fmaxf(mrow0, mx0), mn1 = fmaxf(mrow1, mx1);                 \
        float al0 = ex2(mrow0 - mn0), al1 = ex2(mrow1 - mn1);                   \
        mrow0 = mn0; mrow1 = mn1;                                               \
        float rs0 = 0.f, rs1 = 0.f;                                             \
        _Pragma("unroll")                                                       \
        for (int nt = 0; nt < 8; nt++) {                                        \
            p[nt][0] = ex2(p[nt][0] - mn0); p[nt][1] = ex2(p[nt][1] - mn0);     \
            p[nt][2] = ex2(p[nt][2] - mn1); p[nt][3] = ex2(p[nt][3] - mn1);     \
            rs0 += p[nt][0] + p[nt][1]; rs1 += p[nt][2] + p[nt][3];             \
        }                                                                       \
        rs0 += __shfl_xor_sync(~0u, rs0, 1); rs0 += __shfl_xor_sync(~0u, rs0, 2);\
        rs1 += __shfl_xor_sync(~0u, rs1, 1); rs1 += __shfl_xor_sync(~0u, rs1, 2);\
        lsum0 = lsum0 * al0 + rs0;                                              \
        lsum1 = lsum1 * al1 + rs1;                                              \
        _Pragma("unroll")                                                       \
        for (int nt = 0; nt < 8; nt++) {                                        \
            o[nt][0] *= al0; o[nt][1] *= al0; o[nt][2] *= al1; o[nt][3] *= al1; \
        }                                                                       \
    }

#define CVT_P()                                                                 \
    uint32_t af[4][4];                                                          \
    _Pragma("unroll")                                                           \
    for (int ks = 0; ks < 4; ks++) {                                            \
        af[ks][0] = h2(p[2*ks][0],   p[2*ks][1]);                               \
        af[ks][1] = h2(p[2*ks][2],   p[2*ks][3]);                               \
        af[ks][2] = h2(p[2*ks+1][0], p[2*ks+1][1]);                             \
        af[ks][3] = h2(p[2*ks+1][2], p[2*ks+1][3]);                             \
    }

#define PV16(HALF)                                                              \
    _Pragma("unroll")                                                           \
    for (int ks = 0; ks < 4; ks++) {                                            \
        uint32_t vrow = (uint32_t)((HALF) * 64 + ks * 16) + vrbase;             \
        _Pragma("unroll")                                                       \
        for (int ntt = 0; ntt < 4; ntt++) {                                     \
            uint32_t vb[4];                                                     \
            ldsm4t(vb, sV + (vrow * 72 + ntt * 16 + vcoff) * 2);                \
            mma16h(o[2*ntt],   af[ks], vb,   o[2*ntt]);                         \
            mma16h(o[2*ntt+1], af[ks], vb+2, o[2*ntt+1]);                       \
        }                                                                       \
    }

    for (int it = 0; it < 16; it++) {
        cpwait<1>();          // K(it) landed; V(it) may be pending
        __syncthreads();      // all threads' K(it) visible

        {   // ---- half 0 ----
            float p[8][4];
            AC_MMA(0)
            SOFTMAX_STEP()
            CVT_P()           // p dead after this
            cpwait<0>();      // V(it) complete
            __syncthreads();
            LDBD(it * 128 + 64)   // BD half1 — covered by PV0 + AC1
            PV16(0)
        }
        {   // ---- half 1 ----
            float p[8][4];
            AC_MMA(1)
            SOFTMAX_STEP()
            CVT_P()
            __syncthreads();  // all warps done with Ksh
            if (it + 1 < 16) {
                const __half* kn = Kg + (size_t)((it + 1) * 128) * 2048;
#pragma unroll
                for (int t = 0; t < 4; t++) {
                    int idx = tid + t * 256; int r = idx >> 3, c8 = (idx & 7) << 3;
                    cpa16(sK + (r * 72 + c8) * 2, kn + (size_t)r * 2048 + c8);
                }
                cpcommit();
                LDBD((it + 1) * 128)   // BD next half0 — covered by PV1 + next AC0
            }
            PV16(1)
        }
        __syncthreads();      // all warps done reading Vsh
        if (it + 1 < 16) {
            const __half* vn = Vg + (size_t)((it + 1) * 128) * 2048;
#pragma unroll
            for (int t = 0; t < 4; t++) {
                int idx = tid + t * 256; int r = idx >> 3, c8 = (idx & 7) << 3;
                cpa16(sV + (r * 72 + c8) * 2, vn + (size_t)r * 2048 + c8);
            }
            cpcommit();
        }
    }
#undef LDBD
#undef AC_MMA
#undef SOFTMAX_STEP
#undef CVT_P
#undef PV16

    float inv0 = 1.f / lsum0, inv1 = 1.f / lsum1;
#pragma unroll
    for (int nt = 0; nt < 8; nt++) {
        int c = h * 64 + nt * 8 + 2 * tc;
        *(float2*)(g_att + ((size_t)row0 * B_ + b) * D_ + c) =
            make_float2(o[nt][0] * inv0, o[nt][1] * inv0);
        *(float2*)(g_att + ((size_t)row1 * B_ + b) * D_ + c) =
            make_float2(o[nt][2] * inv1, o[nt][3] * inv1);
    }
}

// ============================================================
// LayerNorm over D=1024 per row.
// ============================================================
__global__ __launch_bounds__(256) void ln_k(const float* __restrict__ gamma,
                                            const float* __restrict__ beta,
                                            float* __restrict__ out)
{
    __shared__ float reds[8], redq[8];
    const float* y = g_y + (size_t)blockIdx.x * D_;
    int tid = threadIdx.x;
    float v[4];
    float s = 0.f, q = 0.f;
#pragma unroll
    for (int t = 0; t < 4; t++) {
        v[t] = y[tid + t * 256];
        s += v[t]; q += v[t] * v[t];
    }
#pragma unroll
    for (int o = 16; o; o >>= 1) {
        s += __shfl_xor_sync(0xffffffffu, s, o);
        q += __shfl_xor_sync(0xffffffffu, q, o);
    }
    if ((tid & 31) == 0) { reds[tid >> 5] = s; redq[tid >> 5] = q; }
    __syncthreads();
    float ts = 0.f, tq = 0.f;
#pragma unroll
    for (int wv = 0; wv < 8; wv++) { ts += reds[wv]; tq += redq[wv]; }
    float mu = ts * (1.f / 1024.f);
    float var = tq * (1.f / 1024.f) - mu * mu;
    float inv = rsqrtf(var + 1e-5f);
    float* op = out + (size_t)blockIdx.x * D_;
#pragma unroll
    for (int t = 0; t < 4; t++) {
        int c = tid + t * 256;
        op[c] = (v[t] - mu) * inv * gamma[c] + beta[c];
    }
}

// ============================================================
extern "C" void kernel_launch(void* const* d_in, const int* in_sizes, int n_in,
                              void* d_out, int out_size)
{
    const float* x    = (const float*)d_in[0];
    const float* pe   = (const float*)d_in[1];
    const float* pbu  = (const float*)d_in[2];
    const float* pbv  = (const float*)d_in[3];
    const float* Wqkv = (const float*)d_in[4];
    const float* Wrel = (const float*)d_in[5];
    const float* Wo   = (const float*)d_in[6];
    const float* gam  = (const float*)d_in[7];
    const float* bet  = (const float*)d_in[8];
    float* out = (float*)d_out;

    const int PG_SMEM = 71680;     // (9216 + 8704) * 4
    const int BD_SMEM = 69632;     // 2 * 128*68 * 4
    const int FA_SMEM = 55296;     // 3 * 128*72 * 2
    cudaFuncSetAttribute(pgemm<0>, cudaFuncAttributeMaxDynamicSharedMemorySize, PG_SMEM);
    cudaFuncSetAttribute(pgemm<1>, cudaFuncAttributeMaxDynamicSharedMemorySize, PG_SMEM);
    cudaFuncSetAttribute(pgemm<2>, cudaFuncAttributeMaxDynamicSharedMemorySize, PG_SMEM);
    cudaFuncSetAttribute(bd_gemm,  cudaFuncAttributeMaxDynamicSharedMemorySize, BD_SMEM);
    cudaFuncSetAttribute(fattn,    cudaFuncAttributeMaxDynamicSharedMemorySize, FA_SMEM);

    // 1) qkv = x @ W_qkv  (q -> f32; k,v -> fp16)
    pgemm<0><<<dim3(24, 32), 256, PG_SMEM>>>(x, Wqkv, nullptr, 3072);
    // 2) r = pos_emb @ W_relemb
    pgemm<1><<<dim3(8, 16), 256, PG_SMEM>>>(pe, Wrel, nullptr, 1024);
    // 3) Draw = (q + pbv) @ r^T per (b,h), fp16 out
    bd_gemm<<<dim3(16, 16, 32), 256, BD_SMEM>>>(pbv);
    // 4) fused: scores + rel-shift + softmax + PV
    fattn<<<dim3(16, 32), 256, FA_SMEM>>>(pbu);
    // 5) y = x + attn_vec @ W_o
    pgemm<2><<<dim3(8, 32), 256, PG_SMEM>>>(nullptr, Wo, x, 1024);
    // 6) layernorm
    ln_k<<<4096, 256>>>(gam, bet, out);
}